// round 13
// baseline (speedup 1.0000x reference)
#include <cuda_runtime.h>
#include <cuda_bf16.h>
#include <math.h>
#include <cstdint>

#define Nn 64
#define Hh 1024
#define FH 4096
#define Tt 512
#define Dd 1024
#define NCTA 128
#define Rr (Tt * Nn)        // 32768 GEMM rows

// ---------------------------------------------------------------------------
// Scratch (static device globals — no runtime allocation allowed)
// ---------------------------------------------------------------------------
__device__ float g_xw[(size_t)Tt * Nn * FH];        // (T*N, 4H) fp32, 512 MB
__device__ float g_h[2][Nn * Hh];                   // ping-pong hidden state
__device__ unsigned g_bar;                          // grid barrier counter
__device__ __nv_bfloat16 g_xhi[(size_t)Rr * Dd];    // x split hi (row r = t*64+n)
__device__ __nv_bfloat16 g_xlo[(size_t)Rr * Dd];    // x split lo
__device__ __nv_bfloat16 g_wthi[(size_t)FH * Dd];   // Wx^T split hi  [c][k]
__device__ __nv_bfloat16 g_wtlo[(size_t)FH * Dd];   // Wx^T split lo

__device__ __forceinline__ uint32_t smem_u32(const void* p) {
    uint32_t a;
    asm("{ .reg .u64 t; cvta.to.shared.u64 t, %1; cvt.u32.u64 %0, t; }"
        : "=r"(a) : "l"(p));
    return a;
}

// packed dual-fp32 helpers (sm_100+/sm_103 f32x2 pipe)
typedef unsigned long long u64t;
#define PACK2(d, lo, hi) \
    asm("mov.b64 %0, {%1, %2};" : "=l"(d) : "f"(lo), "f"(hi))
#define UNPACK2(lo, hi, s) \
    asm("mov.b64 {%0, %1}, %2;" : "=f"(lo), "=f"(hi) : "l"(s))
#define FMA2(acc, a, b) \
    asm("fma.rn.f32x2 %0, %1, %2, %0;" : "+l"(acc) : "l"(a), "l"(b))

// ---------------------------------------------------------------------------
// init: h_buf[0] = h0, reset barrier
// ---------------------------------------------------------------------------
__global__ void init_kernel(const float* __restrict__ h0) {
    int idx = blockIdx.x * blockDim.x + threadIdx.x;
    if (idx < Nn * Hh) g_h[0][idx] = h0[idx];
    if (idx == 0) g_bar = 0;
}

// ---------------------------------------------------------------------------
// split x into bf16 hi/lo, reindexed to GEMM rows r = t*64 + n
// ---------------------------------------------------------------------------
__global__ void split_x(const float* __restrict__ x) {
    size_t q = (size_t)blockIdx.x * blockDim.x + threadIdx.x;  // quad index
    if (q >= (size_t)Rr * Dd / 4) return;
    size_t e = q * 4;
    int r = (int)(e >> 10);
    int k = (int)(e & 1023);
    int n = r & 63, t = r >> 6;
    float4 v = *(const float4*)&x[(size_t)n * Tt * Dd + (size_t)t * Dd + k];
    __nv_bfloat16 h[4], l[4];
    float vv[4] = {v.x, v.y, v.z, v.w};
#pragma unroll
    for (int i = 0; i < 4; i++) {
        h[i] = __float2bfloat16(vv[i]);
        l[i] = __float2bfloat16(vv[i] - __bfloat162float(h[i]));
    }
    *(uint2*)&g_xhi[e] = *(uint2*)h;
    *(uint2*)&g_xlo[e] = *(uint2*)l;
}

// ---------------------------------------------------------------------------
// split + transpose Wx into bf16 hi/lo:  g_wt*[c][k] = split(Wx[k][c])
// ---------------------------------------------------------------------------
__global__ void split_w(const float* __restrict__ Wx) {
    size_t q = (size_t)blockIdx.x * blockDim.x + threadIdx.x;
    if (q >= (size_t)FH * Dd / 4) return;
    size_t e = q * 4;
    int c = (int)(e >> 10);
    int k = (int)(e & 1023);
    __nv_bfloat16 h[4], l[4];
#pragma unroll
    for (int i = 0; i < 4; i++) {
        float v = Wx[(size_t)(k + i) * FH + c];
        h[i] = __float2bfloat16(v);
        l[i] = __float2bfloat16(v - __bfloat162float(h[i]));
    }
    *(uint2*)&g_wthi[e] = *(uint2*)h;
    *(uint2*)&g_wtlo[e] = *(uint2*)l;
}

// ---------------------------------------------------------------------------
// Phase 1 GEMM on HMMA (mma.sync bf16): g_xw = x @ Wx + b, 3-term split.
// (byte-identical to the R9 pass)
// ---------------------------------------------------------------------------
#define LDA_S 72

__global__ __launch_bounds__(256, 1) void xw_tc(const float* __restrict__ b) {
    __shared__ alignas(16) __nv_bfloat16 sA[128 * LDA_S];   // [m][k]
    __shared__ alignas(16) __nv_bfloat16 sB[128 * LDA_S];   // [n][k]

    const int tid = threadIdx.x;
    const int wid = tid >> 5;
    const int lane = tid & 31;
    const int rBase = blockIdx.y * 128;
    const int cBase = blockIdx.x * 128;

    const int wm = (wid >> 2) * 64;
    const int wn = (wid & 3) * 32;

    const uint32_t saA = smem_u32(sA);
    const uint32_t saB = smem_u32(sB);

    const uint32_t aRow = wm + (lane & 15);
    const uint32_t aCol = (lane >> 4) * 8;
    const uint32_t bRow = wn + ((lane >> 4) & 1) * 8 + (lane & 7);
    const uint32_t bCol = ((lane >> 3) & 1) * 8;

    float acc[4][4][4];
#pragma unroll
    for (int i = 0; i < 4; i++)
#pragma unroll
        for (int j = 0; j < 4; j++)
#pragma unroll
            for (int f = 0; f < 4; f++) acc[i][j][f] = 0.0f;

    const __nv_bfloat16* Asrc[3] = {g_xhi, g_xhi, g_xlo};
    const __nv_bfloat16* Bsrc[3] = {g_wthi, g_wtlo, g_wthi};

    float4 ra[4], rb[4];
    const int row_[4] = {tid >> 3, (tid + 256) >> 3, (tid + 512) >> 3, (tid + 768) >> 3};
    const int seg_[4] = {tid & 7, (tid + 256) & 7, (tid + 512) & 7, (tid + 768) & 7};

#pragma unroll
    for (int qq = 0; qq < 4; qq++) {
        ra[qq] = *(const float4*)&Asrc[0][(size_t)(rBase + row_[qq]) * Dd + seg_[qq] * 8];
        rb[qq] = *(const float4*)&Bsrc[0][(size_t)(cBase + row_[qq]) * Dd + seg_[qq] * 8];
    }

    for (int c = 0; c < 48; c++) {
#pragma unroll
        for (int qq = 0; qq < 4; qq++) {
            *(float4*)&sA[row_[qq] * LDA_S + seg_[qq] * 8] = ra[qq];
            *(float4*)&sB[row_[qq] * LDA_S + seg_[qq] * 8] = rb[qq];
        }
        __syncthreads();

        if (c < 47) {
            int nc = c + 1;
            int p = nc >> 4;
            int kc = (nc & 15) * 64;
            const __nv_bfloat16* ap = Asrc[p];
            const __nv_bfloat16* bp = Bsrc[p];
#pragma unroll
            for (int qq = 0; qq < 4; qq++) {
                ra[qq] = *(const float4*)&ap[(size_t)(rBase + row_[qq]) * Dd + kc + seg_[qq] * 8];
                rb[qq] = *(const float4*)&bp[(size_t)(cBase + row_[qq]) * Dd + kc + seg_[qq] * 8];
            }
        }

#pragma unroll
        for (int ks = 0; ks < 4; ks++) {
            const uint32_t kb = ks * 16;
            uint32_t af[4][4];
            uint32_t bf[2][4];
#pragma unroll
            for (int i = 0; i < 4; i++) {
                uint32_t addr = saA + ((aRow + i * 16) * LDA_S + kb + aCol) * 2;
                asm volatile(
                    "ldmatrix.sync.aligned.m8n8.x4.shared.b16 {%0,%1,%2,%3}, [%4];"
                    : "=r"(af[i][0]), "=r"(af[i][1]), "=r"(af[i][2]), "=r"(af[i][3])
                    : "r"(addr));
            }
#pragma unroll
            for (int jp = 0; jp < 2; jp++) {
                uint32_t addr = saB + ((bRow + jp * 16) * LDA_S + kb + bCol) * 2;
                asm volatile(
                    "ldmatrix.sync.aligned.m8n8.x4.shared.b16 {%0,%1,%2,%3}, [%4];"
                    : "=r"(bf[jp][0]), "=r"(bf[jp][1]), "=r"(bf[jp][2]), "=r"(bf[jp][3])
                    : "r"(addr));
            }
#pragma unroll
            for (int i = 0; i < 4; i++)
#pragma unroll
                for (int j = 0; j < 4; j++) {
                    uint32_t b0 = bf[j >> 1][(j & 1) * 2 + 0];
                    uint32_t b1 = bf[j >> 1][(j & 1) * 2 + 1];
                    asm volatile(
                        "mma.sync.aligned.m16n8k16.row.col.f32.bf16.bf16.f32 "
                        "{%0,%1,%2,%3}, {%4,%5,%6,%7}, {%8,%9}, {%0,%1,%2,%3};"
                        : "+f"(acc[i][j][0]), "+f"(acc[i][j][1]),
                          "+f"(acc[i][j][2]), "+f"(acc[i][j][3])
                        : "r"(af[i][0]), "r"(af[i][1]), "r"(af[i][2]), "r"(af[i][3]),
                          "r"(b0), "r"(b1));
                }
        }
        __syncthreads();
    }

    const int er = lane >> 2;
    const int ec = (lane & 3) * 2;
#pragma unroll
    for (int i = 0; i < 4; i++) {
        const size_t r0 = (size_t)(rBase + wm + i * 16 + er);
        const size_t r1 = r0 + 8;
#pragma unroll
        for (int j = 0; j < 4; j++) {
            const int cc = cBase + wn + j * 8 + ec;
            float2 bb = *(const float2*)&b[cc];
            float2 o0 = make_float2(acc[i][j][0] + bb.x, acc[i][j][1] + bb.y);
            float2 o1 = make_float2(acc[i][j][2] + bb.x, acc[i][j][3] + bb.y);
            *(float2*)&g_xw[r0 * FH + cc] = o0;
            *(float2*)&g_xw[r1 * FH + cc] = o1;
        }
    }
}

// ---------------------------------------------------------------------------
// Phase 2: persistent fused LSTM (R6-proven structure), inner loop upgraded
// to packed fma.rn.f32x2: acc pairs over row-pairs (free packs from the
// float4 h load), w broadcast packed with one MOV each.
// Dyn smem: ws 1024*32 + h double buffer 2*32*68 = 148480 B. (unchanged)
// ---------------------------------------------------------------------------
extern __shared__ float sdyn[];

__global__ __launch_bounds__(256) void lstm_persist(const float* __restrict__ Wh,
                                                    float* __restrict__ out) {
    float* ws = sdyn;                 // [1024][32]
    float* hb = sdyn + 32768;         // [2][32][68]

    const int tid = threadIdx.x;
    const int cp = tid & 15;
    const int rg = tid >> 4;
    const int j0 = blockIdx.x * 8;

    for (int idx = tid; idx < 8192; idx += 256) {
        int k = idx >> 3, seg = idx & 7, g = seg >> 1, hf = seg & 1;
        float4 v = *(const float4*)&Wh[(size_t)k * FH + g * Hh + j0 + hf * 4];
        *(float4*)&ws[k * 32 + seg * 4] = v;
    }

    const int en0 = tid >> 3, ej0 = tid & 7;
    const int en1 = (tid + 256) >> 3, ej1 = (tid + 256) & 7;
    float creg0 = 0.0f, creg1 = 0.0f;

    const int ln0 = tid >> 3, lk0 = tid & 7;
    const int ln1 = (tid + 256) >> 3, lk1 = (tid + 256) & 7;

    __syncthreads();

    for (int t = 0; t < Tt; t++) {
        const float* __restrict__ hprev = g_h[t & 1];
        float* __restrict__ hnext = g_h[(t + 1) & 1];
        const float* __restrict__ xwt = g_xw + (size_t)t * Nn * FH;

        // init packed acc from xw slab:
        // aP[i2][j] = (a[2*i2][j], a[2*i2+1][j]), rows = rg*4 + ...
        u64t aP00, aP01, aP10, aP11;
        {
            float xv[4][2];
#pragma unroll
            for (int i = 0; i < 4; i++)
#pragma unroll
                for (int j = 0; j < 2; j++) {
                    int cc = 2 * cp + j;
                    int gcol = (cc >> 3) * Hh + j0 + (cc & 7);
                    xv[i][j] = __ldg(&xwt[(size_t)(rg * 4 + i) * FH + gcol]);
                }
            PACK2(aP00, xv[0][0], xv[1][0]);
            PACK2(aP10, xv[2][0], xv[3][0]);
            PACK2(aP01, xv[0][1], xv[1][1]);
            PACK2(aP11, xv[2][1], xv[3][1]);
        }

        float4 p0 = __ldcg((const float4*)&hprev[ln0 * Hh + lk0 * 4]);
        float4 p1 = __ldcg((const float4*)&hprev[ln1 * Hh + lk1 * 4]);
        {
            float* b0 = hb;
            b0[(lk0 * 4 + 0) * 68 + ln0] = p0.x;
            b0[(lk0 * 4 + 1) * 68 + ln0] = p0.y;
            b0[(lk0 * 4 + 2) * 68 + ln0] = p0.z;
            b0[(lk0 * 4 + 3) * 68 + ln0] = p0.w;
            b0[(lk1 * 4 + 0) * 68 + ln1] = p1.x;
            b0[(lk1 * 4 + 1) * 68 + ln1] = p1.y;
            b0[(lk1 * 4 + 2) * 68 + ln1] = p1.z;
            b0[(lk1 * 4 + 3) * 68 + ln1] = p1.w;
        }
        __syncthreads();

        for (int tile = 0; tile < 32; tile++) {
            const float* cur = hb + (tile & 1) * 2176;
            const float* wsp = ws + tile * 1024;

            if (tile < 31) {
                int k0n = (tile + 1) * 32;
                p0 = __ldcg((const float4*)&hprev[ln0 * Hh + k0n + lk0 * 4]);
                p1 = __ldcg((const float4*)&hprev[ln1 * Hh + k0n + lk1 * 4]);
            }

#pragma unroll
            for (int kk = 0; kk < 32; kk++) {
                float4 hv = *(const float4*)&cur[kk * 68 + rg * 4];
                float2 wv = *(const float2*)&wsp[kk * 32 + 2 * cp];
                u64t h01, h23, wxx, wyy;
                PACK2(h01, hv.x, hv.y);
                PACK2(h23, hv.z, hv.w);
                PACK2(wxx, wv.x, wv.x);
                PACK2(wyy, wv.y, wv.y);
                FMA2(aP00, h01, wxx);
                FMA2(aP10, h23, wxx);
                FMA2(aP01, h01, wyy);
                FMA2(aP11, h23, wyy);
            }

            if (tile < 31) {
                float* nxt = hb + ((tile + 1) & 1) * 2176;
                nxt[(lk0 * 4 + 0) * 68 + ln0] = p0.x;
                nxt[(lk0 * 4 + 1) * 68 + ln0] = p0.y;
                nxt[(lk0 * 4 + 2) * 68 + ln0] = p0.z;
                nxt[(lk0 * 4 + 3) * 68 + ln0] = p0.w;
                nxt[(lk1 * 4 + 0) * 68 + ln1] = p1.x;
                nxt[(lk1 * 4 + 1) * 68 + ln1] = p1.y;
                nxt[(lk1 * 4 + 2) * 68 + ln1] = p1.z;
                nxt[(lk1 * 4 + 3) * 68 + ln1] = p1.w;
                __syncthreads();
            }
        }

        __syncthreads();
        float* sa = hb;
        {
            float v0, v1;
            UNPACK2(v0, v1, aP00);
            sa[(rg * 4 + 0) * 33 + 2 * cp] = v0;
            sa[(rg * 4 + 1) * 33 + 2 * cp] = v1;
            UNPACK2(v0, v1, aP10);
            sa[(rg * 4 + 2) * 33 + 2 * cp] = v0;
            sa[(rg * 4 + 3) * 33 + 2 * cp] = v1;
            UNPACK2(v0, v1, aP01);
            sa[(rg * 4 + 0) * 33 + 2 * cp + 1] = v0;
            sa[(rg * 4 + 1) * 33 + 2 * cp + 1] = v1;
            UNPACK2(v0, v1, aP11);
            sa[(rg * 4 + 2) * 33 + 2 * cp + 1] = v0;
            sa[(rg * 4 + 3) * 33 + 2 * cp + 1] = v1;
        }
        __syncthreads();

        {
            float ai = sa[en0 * 33 + ej0];
            float af = sa[en0 * 33 + 8 + ej0];
            float ao = sa[en0 * 33 + 16 + ej0];
            float ag = sa[en0 * 33 + 24 + ej0];
            float ig = 1.0f / (1.0f + expf(-ai));
            float fg = 1.0f / (1.0f + expf(-af));
            float og = 1.0f / (1.0f + expf(-ao));
            float gg = tanhf(ag);
            creg0 = fg * creg0 + ig * gg;
            float h = og * tanhf(creg0);
            int col = j0 + ej0;
            hnext[en0 * Hh + col] = h;
            out[(size_t)en0 * Tt * Hh + (size_t)t * Hh + col] = h;
        }
        {
            float ai = sa[en1 * 33 + ej1];
            float af = sa[en1 * 33 + 8 + ej1];
            float ao = sa[en1 * 33 + 16 + ej1];
            float ag = sa[en1 * 33 + 24 + ej1];
            float ig = 1.0f / (1.0f + expf(-ai));
            float fg = 1.0f / (1.0f + expf(-af));
            float og = 1.0f / (1.0f + expf(-ao));
            float gg = tanhf(ag);
            creg1 = fg * creg1 + ig * gg;
            float h = og * tanhf(creg1);
            int col = j0 + ej1;
            hnext[en1 * Hh + col] = h;
            out[(size_t)en1 * Tt * Hh + (size_t)t * Hh + col] = h;
        }

        if (t < Tt - 1) {
            __threadfence();
            __syncthreads();
            if (tid == 0) {
                atomicAdd(&g_bar, 1u);
                unsigned target = (unsigned)NCTA * (unsigned)(t + 1);
                while (*(volatile unsigned*)&g_bar < target) { }
                __threadfence();
            }
            __syncthreads();
        }
    }
}

// ---------------------------------------------------------------------------
// launch
// ---------------------------------------------------------------------------
extern "C" void kernel_launch(void* const* d_in, const int* in_sizes, int n_in,
                              void* d_out, int out_size) {
    const float* x  = (const float*)d_in[0];   // (N, T, D)
    const float* h0 = (const float*)d_in[1];   // (N, H)
    const float* Wx = (const float*)d_in[2];   // (D, 4H)
    const float* Wh = (const float*)d_in[3];   // (H, 4H)
    const float* b  = (const float*)d_in[4];   // (4H,)
    float* out = (float*)d_out;                // (N, T, H)

    static int smem_set = 0;
    const int dyn_smem_p2 = (32768 + 2 * 32 * 68) * 4;   // 148480 B
    if (!smem_set) {
        cudaFuncSetAttribute(lstm_persist,
                             cudaFuncAttributeMaxDynamicSharedMemorySize,
                             dyn_smem_p2);
        smem_set = 1;
    }

    init_kernel<<<(Nn * Hh + 255) / 256, 256>>>(h0);

    // phase-1 prep: bf16 splits
    split_x<<<(int)(((size_t)Rr * Dd / 4 + 255) / 256), 256>>>(x);
    split_w<<<(int)(((size_t)FH * Dd / 4 + 255) / 256), 256>>>(Wx);

    // phase-1 GEMM on HMMA tensor cores
    dim3 g1(FH / 128, Rr / 128);     // (32, 256)
    xw_tc<<<g1, 256>>>(b);

    // phase-2 persistent recurrence (f32x2)
    lstm_persist<<<NCTA, 256, dyn_smem_p2>>>(Wh, out);
}

// round 15
// speedup vs baseline: 1.0379x; 1.0379x over previous
#include <cuda_runtime.h>
#include <cuda_bf16.h>
#include <math.h>
#include <cstdint>

#define Nn 64
#define Hh 1024
#define FH 4096
#define Tt 512
#define Dd 1024
#define NCTA 128
#define Rr (Tt * Nn)        // 32768 GEMM rows

// ---------------------------------------------------------------------------
// Scratch (static device globals — no runtime allocation allowed)
// ---------------------------------------------------------------------------
__device__ float g_xw[(size_t)Tt * Nn * FH];        // (T*N, 4H) fp32, 512 MB
__device__ float g_h[2][Nn * Hh];                   // ping-pong hidden state
__device__ unsigned g_bar;                          // grid barrier counter
__device__ __nv_bfloat16 g_xhi[(size_t)Rr * Dd];    // x split hi (row r = t*64+n)
__device__ __nv_bfloat16 g_xlo[(size_t)Rr * Dd];    // x split lo
__device__ __nv_bfloat16 g_wthi[(size_t)FH * Dd];   // Wx^T split hi  [c][k]
__device__ __nv_bfloat16 g_wtlo[(size_t)FH * Dd];   // Wx^T split lo

__device__ __forceinline__ uint32_t smem_u32(const void* p) {
    uint32_t a;
    asm("{ .reg .u64 t; cvta.to.shared.u64 t, %1; cvt.u32.u64 %0, t; }"
        : "=r"(a) : "l"(p));
    return a;
}

// ---------------------------------------------------------------------------
// init: h_buf[0] = h0, reset barrier
// ---------------------------------------------------------------------------
__global__ void init_kernel(const float* __restrict__ h0) {
    int idx = blockIdx.x * blockDim.x + threadIdx.x;
    if (idx < Nn * Hh) g_h[0][idx] = h0[idx];
    if (idx == 0) g_bar = 0;
}

// ---------------------------------------------------------------------------
// split x into bf16 hi/lo, reindexed to GEMM rows r = t*64 + n
// ---------------------------------------------------------------------------
__global__ void split_x(const float* __restrict__ x) {
    size_t q = (size_t)blockIdx.x * blockDim.x + threadIdx.x;  // quad index
    if (q >= (size_t)Rr * Dd / 4) return;
    size_t e = q * 4;
    int r = (int)(e >> 10);
    int k = (int)(e & 1023);
    int n = r & 63, t = r >> 6;
    float4 v = *(const float4*)&x[(size_t)n * Tt * Dd + (size_t)t * Dd + k];
    __nv_bfloat16 h[4], l[4];
    float vv[4] = {v.x, v.y, v.z, v.w};
#pragma unroll
    for (int i = 0; i < 4; i++) {
        h[i] = __float2bfloat16(vv[i]);
        l[i] = __float2bfloat16(vv[i] - __bfloat162float(h[i]));
    }
    *(uint2*)&g_xhi[e] = *(uint2*)h;
    *(uint2*)&g_xlo[e] = *(uint2*)l;
}

// ---------------------------------------------------------------------------
// split + transpose Wx into bf16 hi/lo via 32x32 smem tile:
// g_wt*[c][k] = split(Wx[k][c]); both global sides coalesced.
// grid (FH/32, Dd/32), block (32, 8)
// ---------------------------------------------------------------------------
__global__ void split_wT(const float* __restrict__ W) {
    __shared__ float tile[32][33];
    const int tx = threadIdx.x, ty = threadIdx.y;
    const int c0 = blockIdx.x * 32;
    const int k0 = blockIdx.y * 32;
#pragma unroll
    for (int r = ty; r < 32; r += 8)
        tile[r][tx] = W[(size_t)(k0 + r) * FH + c0 + tx];
    __syncthreads();
#pragma unroll
    for (int r = ty; r < 32; r += 8) {
        float v = tile[tx][r];               // = W[k0+tx][c0+r]
        __nv_bfloat16 hi = __float2bfloat16(v);
        __nv_bfloat16 lo = __float2bfloat16(v - __bfloat162float(hi));
        size_t o = (size_t)(c0 + r) * Dd + k0 + tx;
        g_wthi[o] = hi;
        g_wtlo[o] = lo;
    }
}

// ---------------------------------------------------------------------------
// Phase 1 GEMM on HMMA (mma.sync bf16): g_xw = x @ Wx + b, 3-term split.
// R9 core with DOUBLE-BUFFERED smem (one __syncthreads per chunk):
// per chunk: issue LDG prefetch (c+1) -> full ldmatrix/mma on buf[c&1]
// (hides LDG latency) -> STS into buf[(c+1)&1] -> sync.
// Dyn smem: A0 18432 | A1 18432 | B0 18432 | B1 18432 = 73728 B.
// ---------------------------------------------------------------------------
#define LDA_S 72
#define ABUF_B (128 * LDA_S * 2)   // 18432 bytes per buffer

__global__ __launch_bounds__(256, 1) void xw_tc(const float* __restrict__ b) {
    extern __shared__ char smp[];
    __nv_bfloat16* sA0 = (__nv_bfloat16*)(smp);
    __nv_bfloat16* sB0 = (__nv_bfloat16*)(smp + 2 * ABUF_B);

    const int tid = threadIdx.x;
    const int wid = tid >> 5;
    const int lane = tid & 31;
    const int rBase = blockIdx.y * 128;
    const int cBase = blockIdx.x * 128;

    const int wm = (wid >> 2) * 64;
    const int wn = (wid & 3) * 32;

    const uint32_t saA = smem_u32(sA0);
    const uint32_t saB = smem_u32(sB0);

    const uint32_t aRow = wm + (lane & 15);
    const uint32_t aCol = (lane >> 4) * 8;
    const uint32_t bRow = wn + ((lane >> 4) & 1) * 8 + (lane & 7);
    const uint32_t bCol = ((lane >> 3) & 1) * 8;

    float acc[4][4][4];
#pragma unroll
    for (int i = 0; i < 4; i++)
#pragma unroll
        for (int j = 0; j < 4; j++)
#pragma unroll
            for (int f = 0; f < 4; f++) acc[i][j][f] = 0.0f;

    const __nv_bfloat16* Asrc[3] = {g_xhi, g_xhi, g_xlo};
    const __nv_bfloat16* Bsrc[3] = {g_wthi, g_wtlo, g_wthi};

    float4 ra[4], rb[4];
    const int row_[4] = {tid >> 3, (tid + 256) >> 3, (tid + 512) >> 3, (tid + 768) >> 3};
    const int seg_[4] = {tid & 7, (tid + 256) & 7, (tid + 512) & 7, (tid + 768) & 7};

    // prologue: load chunk 0, store into buffer 0
#pragma unroll
    for (int qq = 0; qq < 4; qq++) {
        ra[qq] = *(const float4*)&Asrc[0][(size_t)(rBase + row_[qq]) * Dd + seg_[qq] * 8];
        rb[qq] = *(const float4*)&Bsrc[0][(size_t)(cBase + row_[qq]) * Dd + seg_[qq] * 8];
    }
#pragma unroll
    for (int qq = 0; qq < 4; qq++) {
        *(float4*)&sA0[row_[qq] * LDA_S + seg_[qq] * 8] = ra[qq];
        *(float4*)&sB0[row_[qq] * LDA_S + seg_[qq] * 8] = rb[qq];
    }
    __syncthreads();

    for (int c = 0; c < 48; c++) {
        // prefetch chunk c+1 from global (latency hidden under mma below)
        if (c < 47) {
            int nc = c + 1;
            int p = nc >> 4;
            int kc = (nc & 15) * 64;
            const __nv_bfloat16* ap = Asrc[p];
            const __nv_bfloat16* bp = Bsrc[p];
#pragma unroll
            for (int qq = 0; qq < 4; qq++) {
                ra[qq] = *(const float4*)&ap[(size_t)(rBase + row_[qq]) * Dd + kc + seg_[qq] * 8];
                rb[qq] = *(const float4*)&bp[(size_t)(cBase + row_[qq]) * Dd + kc + seg_[qq] * 8];
            }
        }

        // full mma block on buffer (c&1)
        const uint32_t aOff = (uint32_t)(c & 1) * ABUF_B;
#pragma unroll
        for (int ks = 0; ks < 4; ks++) {
            const uint32_t kb = ks * 16;
            uint32_t af[4][4];
            uint32_t bf[2][4];
#pragma unroll
            for (int i = 0; i < 4; i++) {
                uint32_t addr = saA + aOff + ((aRow + i * 16) * LDA_S + kb + aCol) * 2;
                asm volatile(
                    "ldmatrix.sync.aligned.m8n8.x4.shared.b16 {%0,%1,%2,%3}, [%4];"
                    : "=r"(af[i][0]), "=r"(af[i][1]), "=r"(af[i][2]), "=r"(af[i][3])
                    : "r"(addr));
            }
#pragma unroll
            for (int jp = 0; jp < 2; jp++) {
                uint32_t addr = saB + aOff + ((bRow + jp * 16) * LDA_S + kb + bCol) * 2;
                asm volatile(
                    "ldmatrix.sync.aligned.m8n8.x4.shared.b16 {%0,%1,%2,%3}, [%4];"
                    : "=r"(bf[jp][0]), "=r"(bf[jp][1]), "=r"(bf[jp][2]), "=r"(bf[jp][3])
                    : "r"(addr));
            }
#pragma unroll
            for (int i = 0; i < 4; i++)
#pragma unroll
                for (int j = 0; j < 4; j++) {
                    uint32_t b0 = bf[j >> 1][(j & 1) * 2 + 0];
                    uint32_t b1 = bf[j >> 1][(j & 1) * 2 + 1];
                    asm volatile(
                        "mma.sync.aligned.m16n8k16.row.col.f32.bf16.bf16.f32 "
                        "{%0,%1,%2,%3}, {%4,%5,%6,%7}, {%8,%9}, {%0,%1,%2,%3};"
                        : "+f"(acc[i][j][0]), "+f"(acc[i][j][1]),
                          "+f"(acc[i][j][2]), "+f"(acc[i][j][3])
                        : "r"(af[i][0]), "r"(af[i][1]), "r"(af[i][2]), "r"(af[i][3]),
                          "r"(b0), "r"(b1));
                }
        }

        // store prefetched chunk into the OTHER buffer, then one sync
        if (c < 47) {
            __nv_bfloat16* dA = sA0 + ((c + 1) & 1) * (ABUF_B / 2);
            __nv_bfloat16* dB = sB0 + ((c + 1) & 1) * (ABUF_B / 2);
#pragma unroll
            for (int qq = 0; qq < 4; qq++) {
                *(float4*)&dA[row_[qq] * LDA_S + seg_[qq] * 8] = ra[qq];
                *(float4*)&dB[row_[qq] * LDA_S + seg_[qq] * 8] = rb[qq];
            }
            __syncthreads();
        }
    }

    const int er = lane >> 2;
    const int ec = (lane & 3) * 2;
#pragma unroll
    for (int i = 0; i < 4; i++) {
        const size_t r0 = (size_t)(rBase + wm + i * 16 + er);
        const size_t r1 = r0 + 8;
#pragma unroll
        for (int j = 0; j < 4; j++) {
            const int cc = cBase + wn + j * 8 + ec;
            float2 bb = *(const float2*)&b[cc];
            float2 o0 = make_float2(acc[i][j][0] + bb.x, acc[i][j][1] + bb.y);
            float2 o1 = make_float2(acc[i][j][2] + bb.x, acc[i][j][3] + bb.y);
            *(float2*)&g_xw[r0 * FH + cc] = o0;
            *(float2*)&g_xw[r1 * FH + cc] = o1;
        }
    }
}

// ---------------------------------------------------------------------------
// Phase 2: persistent fused LSTM (R6/R9-proven FFMA version, verbatim).
// Dyn smem: ws 1024*32 + h double buffer 2*32*68 = 148480 B.
// ---------------------------------------------------------------------------
extern __shared__ float sdyn[];

__global__ __launch_bounds__(256) void lstm_persist(const float* __restrict__ Wh,
                                                    float* __restrict__ out) {
    float* ws = sdyn;                 // [1024][32]
    float* hb = sdyn + 32768;         // [2][32][68]

    const int tid = threadIdx.x;
    const int cp = tid & 15;
    const int rg = tid >> 4;
    const int j0 = blockIdx.x * 8;

    for (int idx = tid; idx < 8192; idx += 256) {
        int k = idx >> 3, seg = idx & 7, g = seg >> 1, hf = seg & 1;
        float4 v = *(const float4*)&Wh[(size_t)k * FH + g * Hh + j0 + hf * 4];
        *(float4*)&ws[k * 32 + seg * 4] = v;
    }

    const int en0 = tid >> 3, ej0 = tid & 7;
    const int en1 = (tid + 256) >> 3, ej1 = (tid + 256) & 7;
    float creg0 = 0.0f, creg1 = 0.0f;

    const int ln0 = tid >> 3, lk0 = tid & 7;
    const int ln1 = (tid + 256) >> 3, lk1 = (tid + 256) & 7;

    __syncthreads();

    for (int t = 0; t < Tt; t++) {
        const float* __restrict__ hprev = g_h[t & 1];
        float* __restrict__ hnext = g_h[(t + 1) & 1];
        const float* __restrict__ xwt = g_xw + (size_t)t * Nn * FH;

        float acc[4][2];
#pragma unroll
        for (int i = 0; i < 4; i++)
#pragma unroll
            for (int j = 0; j < 2; j++) {
                int cc = 2 * cp + j;
                int gcol = (cc >> 3) * Hh + j0 + (cc & 7);
                acc[i][j] = __ldg(&xwt[(size_t)(rg * 4 + i) * FH + gcol]);
            }

        float4 p0 = __ldcg((const float4*)&hprev[ln0 * Hh + lk0 * 4]);
        float4 p1 = __ldcg((const float4*)&hprev[ln1 * Hh + lk1 * 4]);
        {
            float* b0 = hb;
            b0[(lk0 * 4 + 0) * 68 + ln0] = p0.x;
            b0[(lk0 * 4 + 1) * 68 + ln0] = p0.y;
            b0[(lk0 * 4 + 2) * 68 + ln0] = p0.z;
            b0[(lk0 * 4 + 3) * 68 + ln0] = p0.w;
            b0[(lk1 * 4 + 0) * 68 + ln1] = p1.x;
            b0[(lk1 * 4 + 1) * 68 + ln1] = p1.y;
            b0[(lk1 * 4 + 2) * 68 + ln1] = p1.z;
            b0[(lk1 * 4 + 3) * 68 + ln1] = p1.w;
        }
        __syncthreads();

        for (int tile = 0; tile < 32; tile++) {
            const float* cur = hb + (tile & 1) * 2176;
            const float* wsp = ws + tile * 1024;

            if (tile < 31) {
                int k0n = (tile + 1) * 32;
                p0 = __ldcg((const float4*)&hprev[ln0 * Hh + k0n + lk0 * 4]);
                p1 = __ldcg((const float4*)&hprev[ln1 * Hh + k0n + lk1 * 4]);
            }

#pragma unroll
            for (int kk = 0; kk < 32; kk++) {
                float4 hv = *(const float4*)&cur[kk * 68 + rg * 4];
                float2 wv = *(const float2*)&wsp[kk * 32 + 2 * cp];
                acc[0][0] += hv.x * wv.x;  acc[0][1] += hv.x * wv.y;
                acc[1][0] += hv.y * wv.x;  acc[1][1] += hv.y * wv.y;
                acc[2][0] += hv.z * wv.x;  acc[2][1] += hv.z * wv.y;
                acc[3][0] += hv.w * wv.x;  acc[3][1] += hv.w * wv.y;
            }

            if (tile < 31) {
                float* nxt = hb + ((tile + 1) & 1) * 2176;
                nxt[(lk0 * 4 + 0) * 68 + ln0] = p0.x;
                nxt[(lk0 * 4 + 1) * 68 + ln0] = p0.y;
                nxt[(lk0 * 4 + 2) * 68 + ln0] = p0.z;
                nxt[(lk0 * 4 + 3) * 68 + ln0] = p0.w;
                nxt[(lk1 * 4 + 0) * 68 + ln1] = p1.x;
                nxt[(lk1 * 4 + 1) * 68 + ln1] = p1.y;
                nxt[(lk1 * 4 + 2) * 68 + ln1] = p1.z;
                nxt[(lk1 * 4 + 3) * 68 + ln1] = p1.w;
                __syncthreads();
            }
        }

        __syncthreads();
        float* sa = hb;
#pragma unroll
        for (int i = 0; i < 4; i++)
#pragma unroll
            for (int j = 0; j < 2; j++)
                sa[(rg * 4 + i) * 33 + 2 * cp + j] = acc[i][j];
        __syncthreads();

        {
            float ai = sa[en0 * 33 + ej0];
            float af = sa[en0 * 33 + 8 + ej0];
            float ao = sa[en0 * 33 + 16 + ej0];
            float ag = sa[en0 * 33 + 24 + ej0];
            float ig = 1.0f / (1.0f + expf(-ai));
            float fg = 1.0f / (1.0f + expf(-af));
            float og = 1.0f / (1.0f + expf(-ao));
            float gg = tanhf(ag);
            creg0 = fg * creg0 + ig * gg;
            float h = og * tanhf(creg0);
            int col = j0 + ej0;
            hnext[en0 * Hh + col] = h;
            out[(size_t)en0 * Tt * Hh + (size_t)t * Hh + col] = h;
        }
        {
            float ai = sa[en1 * 33 + ej1];
            float af = sa[en1 * 33 + 8 + ej1];
            float ao = sa[en1 * 33 + 16 + ej1];
            float ag = sa[en1 * 33 + 24 + ej1];
            float ig = 1.0f / (1.0f + expf(-ai));
            float fg = 1.0f / (1.0f + expf(-af));
            float og = 1.0f / (1.0f + expf(-ao));
            float gg = tanhf(ag);
            creg1 = fg * creg1 + ig * gg;
            float h = og * tanhf(creg1);
            int col = j0 + ej1;
            hnext[en1 * Hh + col] = h;
            out[(size_t)en1 * Tt * Hh + (size_t)t * Hh + col] = h;
        }

        if (t < Tt - 1) {
            __threadfence();
            __syncthreads();
            if (tid == 0) {
                atomicAdd(&g_bar, 1u);
                unsigned target = (unsigned)NCTA * (unsigned)(t + 1);
                while (*(volatile unsigned*)&g_bar < target) { }
                __threadfence();
            }
            __syncthreads();
        }
    }
}

// ---------------------------------------------------------------------------
// launch
// ---------------------------------------------------------------------------
extern "C" void kernel_launch(void* const* d_in, const int* in_sizes, int n_in,
                              void* d_out, int out_size) {
    const float* x  = (const float*)d_in[0];   // (N, T, D)
    const float* h0 = (const float*)d_in[1];   // (N, H)
    const float* Wx = (const float*)d_in[2];   // (D, 4H)
    const float* Wh = (const float*)d_in[3];   // (H, 4H)
    const float* b  = (const float*)d_in[4];   // (4H,)
    float* out = (float*)d_out;                // (N, T, H)

    static int smem_set = 0;
    const int dyn_smem_p2 = (32768 + 2 * 32 * 68) * 4;   // 148480 B
    const int dyn_smem_p1 = 4 * ABUF_B;                  // 73728 B
    if (!smem_set) {
        cudaFuncSetAttribute(lstm_persist,
                             cudaFuncAttributeMaxDynamicSharedMemorySize,
                             dyn_smem_p2);
        cudaFuncSetAttribute(xw_tc,
                             cudaFuncAttributeMaxDynamicSharedMemorySize,
                             dyn_smem_p1);
        smem_set = 1;
    }

    init_kernel<<<(Nn * Hh + 255) / 256, 256>>>(h0);

    // phase-1 prep: bf16 splits
    split_x<<<(int)(((size_t)Rr * Dd / 4 + 255) / 256), 256>>>(x);
    {
        dim3 gb(FH / 32, Dd / 32);   // (128, 32)
        dim3 bb(32, 8);
        split_wT<<<gb, bb>>>(Wx);
    }

    // phase-1 GEMM on HMMA tensor cores (double-buffered)
    dim3 g1(FH / 128, Rr / 128);     // (32, 256)
    xw_tc<<<g1, 256, dyn_smem_p1>>>(b);

    // phase-2 persistent recurrence (FFMA, proven)
    lstm_persist<<<NCTA, 256, dyn_smem_p2>>>(Wh, out);
}

// round 16
// speedup vs baseline: 1.7933x; 1.7279x over previous
#include <cuda_runtime.h>
#include <cuda_bf16.h>
#include <math.h>
#include <cstdint>

#define Nn 64
#define Hh 1024
#define FH 4096
#define Tt 512
#define Dd 1024
#define NCTA 128
#define Rr (Tt * Nn)        // 32768 GEMM rows

// ---------------------------------------------------------------------------
// Scratch (static device globals — no runtime allocation allowed).
// NOTE: these are ONLY referenced inside kernels. Never pass their addresses
// from host code (host-side symbol decay gave the R10/R11 garbage pointer).
// ---------------------------------------------------------------------------
__device__ float g_xw[(size_t)Tt * Nn * FH];        // (T*N, 4H) fp32, 512 MB
__device__ float g_h[2][Nn * Hh];                   // fp32 hidden ping-pong
__device__ unsigned g_bar;                          // grid barrier counter
__device__ __nv_bfloat16 g_xhi[(size_t)Rr * Dd];    // x split hi (row r = t*64+n)
__device__ __nv_bfloat16 g_xlo[(size_t)Rr * Dd];    // x split lo
__device__ __nv_bfloat16 g_wthi[(size_t)FH * Dd];   // Wx^T split hi  [c][k]
__device__ __nv_bfloat16 g_wtlo[(size_t)FH * Dd];   // Wx^T split lo
__device__ __nv_bfloat16 g_whthi[(size_t)FH * Dd];  // Wh^T split hi  [c][k]
__device__ __nv_bfloat16 g_whtlo[(size_t)FH * Dd];  // Wh^T split lo

__device__ __forceinline__ uint32_t smem_u32(const void* p) {
    uint32_t a;
    asm("{ .reg .u64 t; cvta.to.shared.u64 t, %1; cvt.u32.u64 %0, t; }"
        : "=r"(a) : "l"(p));
    return a;
}

// ---------------------------------------------------------------------------
// init: h_buf[0] = h0 (fp32), reset barrier
// ---------------------------------------------------------------------------
__global__ void init_kernel(const float* __restrict__ h0) {
    int idx = blockIdx.x * blockDim.x + threadIdx.x;
    if (idx < Nn * Hh) g_h[0][idx] = h0[idx];
    if (idx == 0) g_bar = 0;
}

// ---------------------------------------------------------------------------
// split x into bf16 hi/lo, reindexed to GEMM rows r = t*64 + n
// ---------------------------------------------------------------------------
__global__ void split_x(const float* __restrict__ x) {
    size_t q = (size_t)blockIdx.x * blockDim.x + threadIdx.x;  // quad index
    if (q >= (size_t)Rr * Dd / 4) return;
    size_t e = q * 4;
    int r = (int)(e >> 10);
    int k = (int)(e & 1023);
    int n = r & 63, t = r >> 6;
    float4 v = *(const float4*)&x[(size_t)n * Tt * Dd + (size_t)t * Dd + k];
    __nv_bfloat16 h[4], l[4];
    float vv[4] = {v.x, v.y, v.z, v.w};
#pragma unroll
    for (int i = 0; i < 4; i++) {
        h[i] = __float2bfloat16(vv[i]);
        l[i] = __float2bfloat16(vv[i] - __bfloat162float(h[i]));
    }
    *(uint2*)&g_xhi[e] = *(uint2*)h;
    *(uint2*)&g_xlo[e] = *(uint2*)l;
}

// ---------------------------------------------------------------------------
// split + transpose Wx into bf16 hi/lo via 32x32 smem tile (proven R15)
// grid (FH/32, Dd/32), block (32, 8)
// ---------------------------------------------------------------------------
__global__ void split_wT(const float* __restrict__ W) {
    __shared__ float tile[32][33];
    const int tx = threadIdx.x, ty = threadIdx.y;
    const int c0 = blockIdx.x * 32;
    const int k0 = blockIdx.y * 32;
#pragma unroll
    for (int r = ty; r < 32; r += 8)
        tile[r][tx] = W[(size_t)(k0 + r) * FH + c0 + tx];
    __syncthreads();
#pragma unroll
    for (int r = ty; r < 32; r += 8) {
        float v = tile[tx][r];
        __nv_bfloat16 hi = __float2bfloat16(v);
        __nv_bfloat16 lo = __float2bfloat16(v - __bfloat162float(hi));
        size_t o = (size_t)(c0 + r) * Dd + k0 + tx;
        g_wthi[o] = hi;
        g_wtlo[o] = lo;
    }
}

// same, but writes the Wh split arrays (separate kernel — globals referenced
// in-kernel, never passed from host)
__global__ void split_whT(const float* __restrict__ W) {
    __shared__ float tile[32][33];
    const int tx = threadIdx.x, ty = threadIdx.y;
    const int c0 = blockIdx.x * 32;
    const int k0 = blockIdx.y * 32;
#pragma unroll
    for (int r = ty; r < 32; r += 8)
        tile[r][tx] = W[(size_t)(k0 + r) * FH + c0 + tx];
    __syncthreads();
#pragma unroll
    for (int r = ty; r < 32; r += 8) {
        float v = tile[tx][r];
        __nv_bfloat16 hi = __float2bfloat16(v);
        __nv_bfloat16 lo = __float2bfloat16(v - __bfloat162float(hi));
        size_t o = (size_t)(c0 + r) * Dd + k0 + tx;
        g_whthi[o] = hi;
        g_whtlo[o] = lo;
    }
}

// ---------------------------------------------------------------------------
// Phase 1 GEMM on HMMA: g_xw = x @ Wx + b, 3-term split, double-buffered.
// (byte-identical to the R15 pass)
// ---------------------------------------------------------------------------
#define LDA_S 72
#define ABUF_B (128 * LDA_S * 2)   // 18432 bytes per buffer

__global__ __launch_bounds__(256, 1) void xw_tc(const float* __restrict__ b) {
    extern __shared__ char smp[];
    __nv_bfloat16* sA0 = (__nv_bfloat16*)(smp);
    __nv_bfloat16* sB0 = (__nv_bfloat16*)(smp + 2 * ABUF_B);

    const int tid = threadIdx.x;
    const int wid = tid >> 5;
    const int lane = tid & 31;
    const int rBase = blockIdx.y * 128;
    const int cBase = blockIdx.x * 128;

    const int wm = (wid >> 2) * 64;
    const int wn = (wid & 3) * 32;

    const uint32_t saA = smem_u32(sA0);
    const uint32_t saB = smem_u32(sB0);

    const uint32_t aRow = wm + (lane & 15);
    const uint32_t aCol = (lane >> 4) * 8;
    const uint32_t bRow = wn + ((lane >> 4) & 1) * 8 + (lane & 7);
    const uint32_t bCol = ((lane >> 3) & 1) * 8;

    float acc[4][4][4];
#pragma unroll
    for (int i = 0; i < 4; i++)
#pragma unroll
        for (int j = 0; j < 4; j++)
#pragma unroll
            for (int f = 0; f < 4; f++) acc[i][j][f] = 0.0f;

    const __nv_bfloat16* Asrc[3] = {g_xhi, g_xhi, g_xlo};
    const __nv_bfloat16* Bsrc[3] = {g_wthi, g_wtlo, g_wthi};

    float4 ra[4], rb[4];
    const int row_[4] = {tid >> 3, (tid + 256) >> 3, (tid + 512) >> 3, (tid + 768) >> 3};
    const int seg_[4] = {tid & 7, (tid + 256) & 7, (tid + 512) & 7, (tid + 768) & 7};

#pragma unroll
    for (int qq = 0; qq < 4; qq++) {
        ra[qq] = *(const float4*)&Asrc[0][(size_t)(rBase + row_[qq]) * Dd + seg_[qq] * 8];
        rb[qq] = *(const float4*)&Bsrc[0][(size_t)(cBase + row_[qq]) * Dd + seg_[qq] * 8];
    }
#pragma unroll
    for (int qq = 0; qq < 4; qq++) {
        *(float4*)&sA0[row_[qq] * LDA_S + seg_[qq] * 8] = ra[qq];
        *(float4*)&sB0[row_[qq] * LDA_S + seg_[qq] * 8] = rb[qq];
    }
    __syncthreads();

    for (int c = 0; c < 48; c++) {
        if (c < 47) {
            int nc = c + 1;
            int p = nc >> 4;
            int kc = (nc & 15) * 64;
            const __nv_bfloat16* ap = Asrc[p];
            const __nv_bfloat16* bp = Bsrc[p];
#pragma unroll
            for (int qq = 0; qq < 4; qq++) {
                ra[qq] = *(const float4*)&ap[(size_t)(rBase + row_[qq]) * Dd + kc + seg_[qq] * 8];
                rb[qq] = *(const float4*)&bp[(size_t)(cBase + row_[qq]) * Dd + kc + seg_[qq] * 8];
            }
        }

        const uint32_t aOff = (uint32_t)(c & 1) * ABUF_B;
#pragma unroll
        for (int ks = 0; ks < 4; ks++) {
            const uint32_t kb = ks * 16;
            uint32_t af[4][4];
            uint32_t bf[2][4];
#pragma unroll
            for (int i = 0; i < 4; i++) {
                uint32_t addr = saA + aOff + ((aRow + i * 16) * LDA_S + kb + aCol) * 2;
                asm volatile(
                    "ldmatrix.sync.aligned.m8n8.x4.shared.b16 {%0,%1,%2,%3}, [%4];"
                    : "=r"(af[i][0]), "=r"(af[i][1]), "=r"(af[i][2]), "=r"(af[i][3])
                    : "r"(addr));
            }
#pragma unroll
            for (int jp = 0; jp < 2; jp++) {
                uint32_t addr = saB + aOff + ((bRow + jp * 16) * LDA_S + kb + bCol) * 2;
                asm volatile(
                    "ldmatrix.sync.aligned.m8n8.x4.shared.b16 {%0,%1,%2,%3}, [%4];"
                    : "=r"(bf[jp][0]), "=r"(bf[jp][1]), "=r"(bf[jp][2]), "=r"(bf[jp][3])
                    : "r"(addr));
            }
#pragma unroll
            for (int i = 0; i < 4; i++)
#pragma unroll
                for (int j = 0; j < 4; j++) {
                    uint32_t b0 = bf[j >> 1][(j & 1) * 2 + 0];
                    uint32_t b1 = bf[j >> 1][(j & 1) * 2 + 1];
                    asm volatile(
                        "mma.sync.aligned.m16n8k16.row.col.f32.bf16.bf16.f32 "
                        "{%0,%1,%2,%3}, {%4,%5,%6,%7}, {%8,%9}, {%0,%1,%2,%3};"
                        : "+f"(acc[i][j][0]), "+f"(acc[i][j][1]),
                          "+f"(acc[i][j][2]), "+f"(acc[i][j][3])
                        : "r"(af[i][0]), "r"(af[i][1]), "r"(af[i][2]), "r"(af[i][3]),
                          "r"(b0), "r"(b1));
                }
        }

        if (c < 47) {
            __nv_bfloat16* dA = sA0 + ((c + 1) & 1) * (ABUF_B / 2);
            __nv_bfloat16* dB = sB0 + ((c + 1) & 1) * (ABUF_B / 2);
#pragma unroll
            for (int qq = 0; qq < 4; qq++) {
                *(float4*)&dA[row_[qq] * LDA_S + seg_[qq] * 8] = ra[qq];
                *(float4*)&dB[row_[qq] * LDA_S + seg_[qq] * 8] = rb[qq];
            }
            __syncthreads();
        }
    }

    const int er = lane >> 2;
    const int ec = (lane & 3) * 2;
#pragma unroll
    for (int i = 0; i < 4; i++) {
        const size_t r0 = (size_t)(rBase + wm + i * 16 + er);
        const size_t r1 = r0 + 8;
#pragma unroll
        for (int j = 0; j < 4; j++) {
            const int cc = cBase + wn + j * 8 + ec;
            float2 bb = *(const float2*)&b[cc];
            float2 o0 = make_float2(acc[i][j][0] + bb.x, acc[i][j][1] + bb.y);
            float2 o1 = make_float2(acc[i][j][2] + bb.x, acc[i][j][3] + bb.y);
            *(float2*)&g_xw[r0 * FH + cc] = o0;
            *(float2*)&g_xw[r1 * FH + cc] = o1;
        }
    }
}

// ---------------------------------------------------------------------------
// Phase 2: persistent fused LSTM on HMMA.
// 128 CTAs x 256 threads (8 warps, 16x16 warp tiles over the 64x32 gate
// tile). CTA owns h-cols [j0, j0+8) -> 32 gate cols; its Wh^T slice (hi+lo)
// lives in smem for the whole kernel. h is fp32 in g_h ping-pong; each
// K=128 chunk is loaded fp32, split to bf16 hi/lo in registers, stored to
// smem, then 3 mma terms (Ahi*Whi + Ahi*Wlo + Alo*Whi) accumulate fp32.
// Epilogue folds xw, applies gates, updates register-resident c.
// Dyn smem: wsHi 66048 | wsLo 66048 | sAhi 17408 | sAlo 17408 | sa 8448
//         = 175360 B.
// ---------------------------------------------------------------------------
#define KPADW 1032
#define APAD 136

__global__ __launch_bounds__(256) void lstm_tc2(float* __restrict__ out) {
    extern __shared__ char sm2[];
    __nv_bfloat16* wsHi = (__nv_bfloat16*)(sm2);
    __nv_bfloat16* wsLo = (__nv_bfloat16*)(sm2 + 66048);
    __nv_bfloat16* sAhi = (__nv_bfloat16*)(sm2 + 132096);
    __nv_bfloat16* sAlo = (__nv_bfloat16*)(sm2 + 149504);
    float* sa = (float*)(sm2 + 166912);   // [64][33]

    const int tid = threadIdx.x;
    const int wid = tid >> 5;
    const int lane = tid & 31;
    const int j0 = blockIdx.x * 8;
    const int wm = (wid & 3) * 16;      // warp m offset (0..48)
    const int wn = (wid >> 2) * 16;     // warp n offset (0 or 16)

    // ---- preload Wh^T slice (gather the CTA's 32 gate-cols), once ----
    for (int idx = tid; idx < 4096; idx += 256) {
        int nl = idx >> 7, seg = idx & 127;
        int gcol = (nl >> 3) * Hh + j0 + (nl & 7);
        *(float4*)&wsHi[nl * KPADW + seg * 8] =
            *(const float4*)&g_whthi[(size_t)gcol * Dd + seg * 8];
        *(float4*)&wsLo[nl * KPADW + seg * 8] =
            *(const float4*)&g_whtlo[(size_t)gcol * Dd + seg * 8];
    }

    const uint32_t wsHiA = smem_u32(wsHi);
    const uint32_t wsLoA = smem_u32(wsLo);
    const uint32_t sAhiA = smem_u32(sAhi);
    const uint32_t sAloA = smem_u32(sAlo);

    const uint32_t aRow = wm + (lane & 15);
    const uint32_t aCol = (lane >> 4) * 8;
    const uint32_t bRow = wn + ((lane >> 4) & 1) * 8 + (lane & 7);
    const uint32_t bCol = ((lane >> 3) & 1) * 8;

    // A chunk load mapping: idx = tid + 256*q -> n = idx>>5, k4 = idx&31
    const int ln[8] = {tid >> 5, (tid + 256) >> 5, (tid + 512) >> 5, (tid + 768) >> 5,
                       (tid + 1024) >> 5, (tid + 1280) >> 5, (tid + 1536) >> 5, (tid + 1792) >> 5};
    const int ls[8] = {tid & 31, (tid + 256) & 31, (tid + 512) & 31, (tid + 768) & 31,
                       (tid + 1024) & 31, (tid + 1280) & 31, (tid + 1536) & 31, (tid + 1792) & 31};

    // epilogue mapping (R6-proven): idx = tid, tid+256 -> (n, jj)
    const int en0 = tid >> 3, ej0 = tid & 7;
    const int en1 = (tid + 256) >> 3, ej1 = (tid + 256) & 7;
    float creg0 = 0.0f, creg1 = 0.0f;

    __syncthreads();

    for (int t = 0; t < Tt; t++) {
        const float* __restrict__ hprev = g_h[t & 1];
        float* __restrict__ hnext = g_h[(t + 1) & 1];
        const float* __restrict__ xwt = g_xw + (size_t)t * Nn * FH;

        float acc[2][4];
#pragma unroll
        for (int j = 0; j < 2; j++)
#pragma unroll
            for (int f = 0; f < 4; f++) acc[j][f] = 0.0f;

        // prefetch chunk 0 (fp32 h, k 0..127)
        float4 rg[8];
#pragma unroll
        for (int q = 0; q < 8; q++)
            rg[q] = *(const float4*)&hprev[ln[q] * Hh + ls[q] * 4];

        for (int c = 0; c < 8; c++) {
            // split to bf16 hi/lo and store chunk c
#pragma unroll
            for (int q = 0; q < 8; q++) {
                float vv[4] = {rg[q].x, rg[q].y, rg[q].z, rg[q].w};
                __nv_bfloat16 hh[4], ll[4];
#pragma unroll
                for (int e = 0; e < 4; e++) {
                    hh[e] = __float2bfloat16(vv[e]);
                    ll[e] = __float2bfloat16(vv[e] - __bfloat162float(hh[e]));
                }
                *(uint2*)&sAhi[ln[q] * APAD + ls[q] * 4] = *(uint2*)hh;
                *(uint2*)&sAlo[ln[q] * APAD + ls[q] * 4] = *(uint2*)ll;
            }
            __syncthreads();

            // prefetch chunk c+1
            if (c < 7) {
                int kc = (c + 1) * 128;
#pragma unroll
                for (int q = 0; q < 8; q++)
                    rg[q] = *(const float4*)&hprev[ln[q] * Hh + kc + ls[q] * 4];
            }

            const uint32_t kkB = (uint32_t)(c * 128);
#pragma unroll
            for (int k16 = 0; k16 < 8; k16++) {
                uint32_t ah[4], al[4], bh[4], bl[4];
                {
                    uint32_t addr = sAhiA + (aRow * APAD + k16 * 16 + aCol) * 2;
                    asm volatile(
                        "ldmatrix.sync.aligned.m8n8.x4.shared.b16 {%0,%1,%2,%3}, [%4];"
                        : "=r"(ah[0]), "=r"(ah[1]), "=r"(ah[2]), "=r"(ah[3])
                        : "r"(addr));
                }
                {
                    uint32_t addr = sAloA + (aRow * APAD + k16 * 16 + aCol) * 2;
                    asm volatile(
                        "ldmatrix.sync.aligned.m8n8.x4.shared.b16 {%0,%1,%2,%3}, [%4];"
                        : "=r"(al[0]), "=r"(al[1]), "=r"(al[2]), "=r"(al[3])
                        : "r"(addr));
                }
                {
                    uint32_t addr = wsHiA + (bRow * KPADW + kkB + k16 * 16 + bCol) * 2;
                    asm volatile(
                        "ldmatrix.sync.aligned.m8n8.x4.shared.b16 {%0,%1,%2,%3}, [%4];"
                        : "=r"(bh[0]), "=r"(bh[1]), "=r"(bh[2]), "=r"(bh[3])
                        : "r"(addr));
                }
                {
                    uint32_t addr = wsLoA + (bRow * KPADW + kkB + k16 * 16 + bCol) * 2;
                    asm volatile(
                        "ldmatrix.sync.aligned.m8n8.x4.shared.b16 {%0,%1,%2,%3}, [%4];"
                        : "=r"(bl[0]), "=r"(bl[1]), "=r"(bl[2]), "=r"(bl[3])
                        : "r"(addr));
                }
#pragma unroll
                for (int j = 0; j < 2; j++) {
                    asm volatile(
                        "mma.sync.aligned.m16n8k16.row.col.f32.bf16.bf16.f32 "
                        "{%0,%1,%2,%3}, {%4,%5,%6,%7}, {%8,%9}, {%0,%1,%2,%3};"
                        : "+f"(acc[j][0]), "+f"(acc[j][1]), "+f"(acc[j][2]), "+f"(acc[j][3])
                        : "r"(ah[0]), "r"(ah[1]), "r"(ah[2]), "r"(ah[3]),
                          "r"(bh[j * 2 + 0]), "r"(bh[j * 2 + 1]));
                    asm volatile(
                        "mma.sync.aligned.m16n8k16.row.col.f32.bf16.bf16.f32 "
                        "{%0,%1,%2,%3}, {%4,%5,%6,%7}, {%8,%9}, {%0,%1,%2,%3};"
                        : "+f"(acc[j][0]), "+f"(acc[j][1]), "+f"(acc[j][2]), "+f"(acc[j][3])
                        : "r"(ah[0]), "r"(ah[1]), "r"(ah[2]), "r"(ah[3]),
                          "r"(bl[j * 2 + 0]), "r"(bl[j * 2 + 1]));
                    asm volatile(
                        "mma.sync.aligned.m16n8k16.row.col.f32.bf16.bf16.f32 "
                        "{%0,%1,%2,%3}, {%4,%5,%6,%7}, {%8,%9}, {%0,%1,%2,%3};"
                        : "+f"(acc[j][0]), "+f"(acc[j][1]), "+f"(acc[j][2]), "+f"(acc[j][3])
                        : "r"(al[0]), "r"(al[1]), "r"(al[2]), "r"(al[3]),
                          "r"(bh[j * 2 + 0]), "r"(bh[j * 2 + 1]));
                }
            }
            __syncthreads();
        }

        // ---- exchange acc via sa (each warp owns a disjoint 16x16 tile) ----
        const int er = lane >> 2, ec = (lane & 3) * 2;
#pragma unroll
        for (int j = 0; j < 2; j++) {
            int r0 = wm + er;
            int c0 = wn + j * 8 + ec;
            sa[r0 * 33 + c0] = acc[j][0];
            sa[r0 * 33 + c0 + 1] = acc[j][1];
            sa[(r0 + 8) * 33 + c0] = acc[j][2];
            sa[(r0 + 8) * 33 + c0 + 1] = acc[j][3];
        }
        __syncthreads();

        // ---- gates + state update (xw folded here) ----
        {
            const size_t xb = (size_t)en0 * FH + j0 + ej0;
            float ai = sa[en0 * 33 + ej0]      + __ldg(&xwt[xb + 0 * Hh]);
            float af = sa[en0 * 33 + 8 + ej0]  + __ldg(&xwt[xb + 1 * Hh]);
            float ao = sa[en0 * 33 + 16 + ej0] + __ldg(&xwt[xb + 2 * Hh]);
            float ag = sa[en0 * 33 + 24 + ej0] + __ldg(&xwt[xb + 3 * Hh]);
            float ig = 1.0f / (1.0f + expf(-ai));
            float fg = 1.0f / (1.0f + expf(-af));
            float og = 1.0f / (1.0f + expf(-ao));
            float gg = tanhf(ag);
            creg0 = fg * creg0 + ig * gg;
            float h = og * tanhf(creg0);
            int col = j0 + ej0;
            hnext[en0 * Hh + col] = h;
            out[(size_t)en0 * Tt * Hh + (size_t)t * Hh + col] = h;
        }
        {
            const size_t xb = (size_t)en1 * FH + j0 + ej1;
            float ai = sa[en1 * 33 + ej1]      + __ldg(&xwt[xb + 0 * Hh]);
            float af = sa[en1 * 33 + 8 + ej1]  + __ldg(&xwt[xb + 1 * Hh]);
            float ao = sa[en1 * 33 + 16 + ej1] + __ldg(&xwt[xb + 2 * Hh]);
            float ag = sa[en1 * 33 + 24 + ej1] + __ldg(&xwt[xb + 3 * Hh]);
            float ig = 1.0f / (1.0f + expf(-ai));
            float fg = 1.0f / (1.0f + expf(-af));
            float og = 1.0f / (1.0f + expf(-ao));
            float gg = tanhf(ag);
            creg1 = fg * creg1 + ig * gg;
            float h = og * tanhf(creg1);
            int col = j0 + ej1;
            hnext[en1 * Hh + col] = h;
            out[(size_t)en1 * Tt * Hh + (size_t)t * Hh + col] = h;
        }

        // ---- grid barrier (R6-proven) ----
        if (t < Tt - 1) {
            __threadfence();
            __syncthreads();
            if (tid == 0) {
                atomicAdd(&g_bar, 1u);
                unsigned target = (unsigned)NCTA * (unsigned)(t + 1);
                while (*(volatile unsigned*)&g_bar < target) { }
                __threadfence();
            }
            __syncthreads();
        } else {
            __syncthreads();
        }
    }
}

// ---------------------------------------------------------------------------
// launch
// ---------------------------------------------------------------------------
extern "C" void kernel_launch(void* const* d_in, const int* in_sizes, int n_in,
                              void* d_out, int out_size) {
    const float* x  = (const float*)d_in[0];   // (N, T, D)
    const float* h0 = (const float*)d_in[1];   // (N, H)
    const float* Wx = (const float*)d_in[2];   // (D, 4H)
    const float* Wh = (const float*)d_in[3];   // (H, 4H)
    const float* b  = (const float*)d_in[4];   // (4H,)
    float* out = (float*)d_out;                // (N, T, H)

    static int smem_set = 0;
    const int dyn_smem_p1 = 4 * ABUF_B;   // 73728 B
    const int dyn_smem_p2 = 175360;
    if (!smem_set) {
        cudaFuncSetAttribute(xw_tc,
                             cudaFuncAttributeMaxDynamicSharedMemorySize,
                             dyn_smem_p1);
        cudaFuncSetAttribute(lstm_tc2,
                             cudaFuncAttributeMaxDynamicSharedMemorySize,
                             dyn_smem_p2);
        smem_set = 1;
    }

    init_kernel<<<(Nn * Hh + 255) / 256, 256>>>(h0);

    // phase-1/2 prep: bf16 splits (globals written INSIDE kernels only)
    split_x<<<(int)(((size_t)Rr * Dd / 4 + 255) / 256), 256>>>(x);
    {
        dim3 gb(FH / 32, Dd / 32);   // (128, 32)
        dim3 bb(32, 8);
        split_wT<<<gb, bb>>>(Wx);
        split_whT<<<gb, bb>>>(Wh);
    }

    // phase-1 GEMM on HMMA (double-buffered)
    dim3 g1(FH / 128, Rr / 128);     // (32, 256)
    xw_tc<<<g1, 256, dyn_smem_p1>>>(b);

    // phase-2 persistent recurrence on HMMA
    lstm_tc2<<<NCTA, 256, dyn_smem_p2>>>(out);
}